// round 13
// baseline (speedup 1.0000x reference)
#include <cuda_runtime.h>

#define T_STEPS 4096
#define NCTA    128
#define NTHR    512

typedef unsigned long long ull;

// ---------------- global scratch (static; no allocs) ----------------
// h layout: [slot][mpair 0..127][b 0..63][2] -> element (m,b) at [m>>1][b][m&1]
// h0(t) at slot t+1 (slot 0 = zeros); h1(t) at slot t+2 (slots 0,1 = zeros)
__device__ __align__(256) float g_h0[4099][128][64][2];
__device__ __align__(256) float g_h1[4099][128][64][2];
__device__ __align__(256) float g_yT[4099][64];   // yT[t+3][b] = y[b][t]; rows 0..2 pad
__device__ unsigned g_prog[NCTA];  // monotone per-CTA progress; re-zeroed in init
__device__ unsigned g_cnt;         // zero-init; reset to 0 each barrier use
__device__ unsigned g_sense;       // zero-init; exactly 2 barrier rounds -> returns to 0

// ---------------- helpers ----------------
__device__ __forceinline__ ull ffma2(ull h, ull w, ull a) {
    ull d;
    asm("fma.rn.f32x2 %0, %1, %2, %3;" : "=l"(d) : "l"(h), "l"(w), "l"(a));
    return d;
}
__device__ __forceinline__ float collapse2(ull a) {   // even-m sum + odd-m sum
    return __uint_as_float((unsigned)a) + __uint_as_float((unsigned)(a >> 32));
}
__device__ __forceinline__ float sigf(float x)   { return 1.0f / (1.0f + __expf(-x)); }
__device__ __forceinline__ float tanh_f(float x) { return 2.0f * sigf(2.0f * x) - 1.0f; }

__device__ __forceinline__ ulonglong2 ldcg2(const float* p) {
    ulonglong2 v;
    asm volatile("ld.global.cg.v2.u64 {%0,%1}, [%2];" : "=l"(v.x), "=l"(v.y) : "l"(p));
    return v;
}
__device__ __forceinline__ unsigned atom_add_acqrel(unsigned* p, unsigned v) {
    unsigned old;
    asm volatile("atom.acq_rel.gpu.global.add.u32 %0, [%1], %2;"
                 : "=r"(old) : "l"(p), "r"(v) : "memory");
    return old;
}
__device__ __forceinline__ unsigned ld_acquire(const unsigned* p) {
    unsigned v;
    asm volatile("ld.acquire.gpu.global.u32 %0, [%1];" : "=r"(v) : "l"(p) : "memory");
    return v;
}
__device__ __forceinline__ void st_release(unsigned* p, unsigned v) {
    asm volatile("st.release.gpu.global.u32 [%0], %1;" :: "l"(p), "r"(v) : "memory");
}
__device__ __forceinline__ void st_relaxed(unsigned* p, unsigned v) {
    asm volatile("st.relaxed.gpu.global.u32 [%0], %1;" :: "l"(p), "r"(v) : "memory");
}

// legacy grid barrier — used exactly twice (init, pre-output)
__device__ __forceinline__ void grid_barrier(int tid, unsigned& ls) {
    __syncthreads();
    ls ^= 1u;
    if (tid == 0) {
        unsigned old = atom_add_acqrel(&g_cnt, 1u);
        if (old == NCTA - 1u) {
            st_relaxed(&g_cnt, 0u);
            st_release(&g_sense, ls);
        } else {
            while (ld_acquire(&g_sense) != ls) { }
        }
    }
    __syncthreads();
}

// ---------------- smem layout (floats) ----------------
//   W0s [8][256]    @ 0      (2048)  W_hh0 rows, plain fp32 K-major
//   W1s [8][256]    @ 2048   (2048)  W_ih1
//   WHs [8][256]    @ 4096   (2048)  W_hh1
//   P0  [16][8][64] @ 6144   (8192)  layer0 gate partials (q, row, batch)
//   P1  [16][8][64] @ 14336  (8192)
//   misc @ 22528: wih0[8][4]=32, b0s[8], b1s[8], yw[4][64]=256, wout[512], bo2[2]
#define SMEM_FLOATS (22528 + 818)
#define SMEM_BYTES  (SMEM_FLOATS * 4)

__global__ void __launch_bounds__(NTHR, 1) lstm_all(
    const float* __restrict__ y,
    const float* __restrict__ Wih0, const float* __restrict__ Whh0,
    const float* __restrict__ bih0, const float* __restrict__ bhh0,
    const float* __restrict__ Wih1, const float* __restrict__ Whh1,
    const float* __restrict__ bih1, const float* __restrict__ bhh1,
    const float* __restrict__ Wout, const float* __restrict__ bout,
    float* __restrict__ out)
{
    extern __shared__ float sm[];
    float* W0s  = sm;              // [8][256]
    float* W1s  = sm + 2048;       // [8][256]
    float* WHs  = sm + 4096;       // [8][256]
    float* P0   = sm + 6144;       // [16][8][64]
    float* P1   = sm + 14336;      // [16][8][64]
    float* wih0 = sm + 22528;      // [8][4]
    float* b0s  = wih0 + 32;       // [8]
    float* b1s  = b0s + 8;         // [8]
    float* yw   = b1s + 8;         // [4][64]
    float* wout = yw + 256;        // [2][256]
    float* bo2  = wout + 512;      // [2]

    const int tid = threadIdx.x;
    const int bid = blockIdx.x;
    const int j0  = bid * 2;                 // CTA owns hidden units j0, j0+1
    unsigned ls = 0;

    // ======== init: global state ========
    {
        int gi = bid * NTHR + tid;           // 0..65535
        if (gi < 16384) ((float*)g_h0)[gi] = 0.0f;   // h0 slot 0 (t = -1)
        if (gi < 32768) ((float*)g_h1)[gi] = 0.0f;   // h1 slots 0,1 (t = -2,-1)
        for (int i = gi; i < 4099 * 64; i += NCTA * NTHR) {
            int row = i >> 6, b = i & 63;
            g_yT[row][b] = (row < 3) ? -100.0f : y[b * T_STEPS + (row - 3)];
        }
        if (tid == 0) st_relaxed(&g_prog[bid], 0u);  // reset own progress counter
    }

    // ======== init: smem weights (plain fp32 rows) ========
    for (int idx = tid; idx < 8 * 256; idx += NTHR) {
        int r = idx >> 8, m = idx & 255;
        int row = (r >> 1) * 256 + j0 + (r & 1);
        W0s[idx] = Whh0[row * 256 + m];
        W1s[idx] = Wih1[row * 256 + m];
        WHs[idx] = Whh1[row * 256 + m];
    }
    if (tid < 8) {
        int row = (tid >> 1) * 256 + j0 + (tid & 1);
        b0s[tid] = bih0[row] + bhh0[row];
        b1s[tid] = bih1[row] + bhh1[row];
        for (int k = 0; k < 4; k++) wih0[tid * 4 + k] = Wih0[row * 4 + k];
    }
    wout[tid] = Wout[tid];                   // exactly 512 elements
    if (tid < 2) bo2[tid] = bout[tid];
    grid_barrier(tid, ls);   // barrier round 1 (orders prog reset & yT/weights)

    // ======== persistent 2-layer LSTM — self-timed dataflow ========
    const int q    = tid >> 5;               // warp id = m-chunk (16 m per chunk)
    const int lane = tid & 31;                // batch pair: batches 2*lane, 2*lane+1
    const float* W0r = W0s + q * 16;
    const float* W1r = W1s + q * 16;
    const float* WHr = WHs + q * 16;
    const int hfl = q * 8 * 128 + 4 * lane;   // float offset of thread's first K-pair

    // this warp's producer CTAs: units 16q..16q+15 -> CTAs 8q..8q+7 (skip self)
    const unsigned* prog8 = g_prog + q * 8;
    const bool pact = (lane < 8) && ((q * 8 + lane) != bid);

    // cell-update role (first 256 threads; c lives in a register)
    const int clb   = tid & 63;
    const int clj   = (tid >> 6) & 1;
    const int chalf = (tid >> 7) & 1;         // 0: layer0 cell, 1: layer1 cell
    float creg = 0.0f;

    for (int p = 0; p <= T_STEPS; p++) {
        // ---- wait for this warp's 8 producers to reach phase p ----
        {
            unsigned v = pact ? ld_acquire(prog8 + lane) : 0xffffffffu;
            while (__ballot_sync(0xffffffffu, pact && (v < (unsigned)p))) {
                if (pact) v = ld_acquire(prog8 + lane);
            }
        }

        const float* H0 = &g_h0[p][0][0][0] + hfl;   // h0(p-1) at slot p
        const float* H1 = &g_h1[p][0][0][0] + hfl;   // h1(p-2) at slot p
        if (tid < 256 && p < T_STEPS) yw[tid] = g_yT[p + (tid >> 6)][tid & 63];

        // h registers: [i].x = batch0 K-pair, [i].y = batch1 K-pair (mp = q*8+i)
        ulonglong2 h0r[8], h1r[8];
        #pragma unroll
        for (int i = 0; i < 8; i++) h0r[i] = ldcg2(H0 + i * 128);
        #pragma unroll
        for (int i = 0; i < 8; i++) h1r[i] = ldcg2(H1 + i * 128);

        // ---- layer0: 8 rows x 16 m x 2 batches ----
        {
            ull aA[8], aB[8];
            #pragma unroll
            for (int r = 0; r < 8; r++) { aA[r] = 0ull; aB[r] = 0ull; }
            #pragma unroll
            for (int mp2 = 0; mp2 < 4; mp2++) {
                const ulonglong2 hE = h0r[2 * mp2], hO = h0r[2 * mp2 + 1];
                #pragma unroll
                for (int r = 0; r < 8; r++) {
                    ulonglong2 wv = *(const ulonglong2*)(W0r + r * 256 + mp2 * 4);
                    aA[r] = ffma2(hE.x, wv.x, aA[r]);
                    aB[r] = ffma2(hE.y, wv.x, aB[r]);
                    aA[r] = ffma2(hO.x, wv.y, aA[r]);
                    aB[r] = ffma2(hO.y, wv.y, aB[r]);
                }
            }
            #pragma unroll
            for (int r = 0; r < 8; r++) {
                float2 v = make_float2(collapse2(aA[r]), collapse2(aB[r]));
                *(float2*)(P0 + q * 512 + r * 64 + 2 * lane) = v;
            }
        }
        // ---- layer1: W_ih1 x h0(p-1) + W_hh1 x h1(p-2) ----
        {
            ull aA[8], aB[8];
            #pragma unroll
            for (int r = 0; r < 8; r++) { aA[r] = 0ull; aB[r] = 0ull; }
            #pragma unroll
            for (int mp2 = 0; mp2 < 4; mp2++) {
                const ulonglong2 hE = h0r[2 * mp2], hO = h0r[2 * mp2 + 1];
                #pragma unroll
                for (int r = 0; r < 8; r++) {
                    ulonglong2 wv = *(const ulonglong2*)(W1r + r * 256 + mp2 * 4);
                    aA[r] = ffma2(hE.x, wv.x, aA[r]);
                    aB[r] = ffma2(hE.y, wv.x, aB[r]);
                    aA[r] = ffma2(hO.x, wv.y, aA[r]);
                    aB[r] = ffma2(hO.y, wv.y, aB[r]);
                }
            }
            #pragma unroll
            for (int mp2 = 0; mp2 < 4; mp2++) {
                const ulonglong2 hE = h1r[2 * mp2], hO = h1r[2 * mp2 + 1];
                #pragma unroll
                for (int r = 0; r < 8; r++) {
                    ulonglong2 wv = *(const ulonglong2*)(WHr + r * 256 + mp2 * 4);
                    aA[r] = ffma2(hE.x, wv.x, aA[r]);
                    aB[r] = ffma2(hE.y, wv.x, aB[r]);
                    aA[r] = ffma2(hO.x, wv.y, aA[r]);
                    aB[r] = ffma2(hO.y, wv.y, aB[r]);
                }
            }
            #pragma unroll
            for (int r = 0; r < 8; r++) {
                float2 v = make_float2(collapse2(aA[r]), collapse2(aB[r]));
                *(float2*)(P1 + q * 512 + r * 64 + 2 * lane) = v;
            }
        }
        __syncthreads();

        // ---- reduce 16 q-partials, cell update, publish h (first 256 threads) ----
        if (tid < 256) {
            const bool act = chalf ? (p > 0) : (p < T_STEPS);
            if (act) {
                const float* P  = chalf ? P1 : P0;
                const float* bs = chalf ? b1s : b0s;
                float gg[4];
                #pragma unroll
                for (int gt = 0; gt < 4; gt++) {
                    int r = gt * 2 + clj;
                    float s = bs[r];
                    #pragma unroll
                    for (int qq = 0; qq < 16; qq++)
                        s += P[qq * 512 + r * 64 + clb];
                    gg[gt] = s;
                }
                if (chalf == 0) {
                    #pragma unroll
                    for (int gt = 0; gt < 4; gt++) {
                        int r = gt * 2 + clj;
                        #pragma unroll
                        for (int k = 0; k < 4; k++)
                            gg[gt] = fmaf(yw[k * 64 + clb], wih0[r * 4 + k], gg[gt]);
                    }
                }
                creg = sigf(gg[1]) * creg + sigf(gg[0]) * tanh_f(gg[2]);
                float h = sigf(gg[3]) * tanh_f(creg);
                int j = j0 + clj;
                if (chalf == 0) g_h0[p + 1][j >> 1][clb][j & 1] = h;   // h0(p)
                else            g_h1[p + 1][j >> 1][clb][j & 1] = h;   // h1(p-1)
            }
        }
        __syncthreads();
        // publish progress: all of this CTA's phase-p h values are now visible
        if (tid == 0) {
            __threadfence();
            st_relaxed(&g_prog[bid], (unsigned)(p + 1));
        }
    }

    grid_barrier(tid, ls);   // barrier round 2 (all h1 finished; sense back to 0)

    // ======== output projection: out[b][t][k] = h1(t).Wout[k] + bout[k] ========
    {
        const int b  = tid & 63;
        const int tt = tid >> 6;    // 0..7
        #pragma unroll
        for (int u = 0; u < 4; u++) {
            int t = bid * 32 + tt * 4 + u;
            const float* h = &g_h1[t + 2][0][0][0] + b * 2;
            float s0 = bo2[0], s1 = bo2[1];
            #pragma unroll 8
            for (int mp = 0; mp < 128; mp++) {
                float2 v = *(const float2*)(h + mp * 128);
                s0 = fmaf(v.x, wout[2 * mp],       s0);
                s0 = fmaf(v.y, wout[2 * mp + 1],   s0);
                s1 = fmaf(v.x, wout[256 + 2 * mp], s1);
                s1 = fmaf(v.y, wout[257 + 2 * mp], s1);
            }
            out[b * (T_STEPS * 2) + t * 2 + 0] = s0;
            out[b * (T_STEPS * 2) + t * 2 + 1] = s1;
        }
    }
}

// ---------------- launcher: ONE kernel ----------------
extern "C" void kernel_launch(void* const* d_in, const int* in_sizes, int n_in,
                              void* d_out, int out_size)
{
    (void)in_sizes; (void)n_in; (void)out_size;
    cudaFuncSetAttribute(lstm_all, cudaFuncAttributeMaxDynamicSharedMemorySize, SMEM_BYTES);
    lstm_all<<<NCTA, NTHR, SMEM_BYTES>>>(
        (const float*)d_in[0],
        (const float*)d_in[1], (const float*)d_in[2],
        (const float*)d_in[3], (const float*)d_in[4],
        (const float*)d_in[5], (const float*)d_in[6],
        (const float*)d_in[7], (const float*)d_in[8],
        (const float*)d_in[9], (const float*)d_in[10],
        (float*)d_out);
}

// round 14
// speedup vs baseline: 1.5048x; 1.5048x over previous
#include <cuda_runtime.h>

#define T_STEPS 4096
#define NCTA    128
#define NTHR    512
#define GCTAS   32          // CTAs per batch-group
#define NGRP    4           // independent batch groups (16 batches each)

typedef unsigned long long ull;

// ---------------- global scratch (static; no allocs) ----------------
// h layout: [slot][mpair 0..127][b 0..63][2] -> element (m,b) at [m>>1][b][m&1]
__device__ __align__(256) float g_h0[3][128][64][2];      // ring: h0(t) at slot (t+1)%3
__device__ __align__(256) float g_h1[4097][128][64][2];   // h1(t) at slot t+1; slot 0 zero
__device__ __align__(256) float g_yT[NGRP][4099][16];     // per-group y windows
__device__ __align__(256) unsigned g_flags[NGRP][32];     // monotone; one 128B line/group
__device__ unsigned g_cnt;    // zero-init; reset each round
__device__ unsigned g_sense;  // zero-init; 2 rounds -> returns to 0

// ---------------- helpers ----------------
__device__ __forceinline__ ull ffma2(ull h, ull w, ull a) {
    ull d;
    asm("fma.rn.f32x2 %0, %1, %2, %3;" : "=l"(d) : "l"(h), "l"(w), "l"(a));
    return d;
}
__device__ __forceinline__ float collapse2(ull a) {
    return __uint_as_float((unsigned)a) + __uint_as_float((unsigned)(a >> 32));
}
__device__ __forceinline__ float sigf(float x)   { return 1.0f / (1.0f + __expf(-x)); }
__device__ __forceinline__ float tanh_f(float x) { return 2.0f * sigf(2.0f * x) - 1.0f; }

__device__ __forceinline__ ulonglong2 ldcg2(const float* p) {
    ulonglong2 v;
    asm volatile("ld.global.cg.v2.u64 {%0,%1}, [%2];" : "=l"(v.x), "=l"(v.y) : "l"(p));
    return v;
}
__device__ __forceinline__ unsigned atom_add_acqrel(unsigned* p, unsigned v) {
    unsigned old;
    asm volatile("atom.acq_rel.gpu.global.add.u32 %0, [%1], %2;"
                 : "=r"(old) : "l"(p), "r"(v) : "memory");
    return old;
}
__device__ __forceinline__ unsigned ld_acquire(const unsigned* p) {
    unsigned v;
    asm volatile("ld.acquire.gpu.global.u32 %0, [%1];" : "=r"(v) : "l"(p) : "memory");
    return v;
}
__device__ __forceinline__ void st_release(unsigned* p, unsigned v) {
    asm volatile("st.release.gpu.global.u32 [%0], %1;" :: "l"(p), "r"(v) : "memory");
}
__device__ __forceinline__ void st_relaxed(unsigned* p, unsigned v) {
    asm volatile("st.relaxed.gpu.global.u32 [%0], %1;" :: "l"(p), "r"(v) : "memory");
}

// global barrier (used exactly twice at the very end)
__device__ __forceinline__ void grid_barrier(int tid, unsigned& ls) {
    __syncthreads();
    ls ^= 1u;
    if (tid == 0) {
        unsigned old = atom_add_acqrel(&g_cnt, 1u);
        if (old == NCTA - 1u) {
            st_relaxed(&g_cnt, 0u);
            st_release(&g_sense, ls);
        } else {
            while (ld_acquire(&g_sense) != ls) { }
        }
    }
    __syncthreads();
}

// ---------------- smem layout (floats) ----------------
#define W0S_OFF   0        // [16q][4 mp2][8 lr][4 rh] float4 = 8192 floats
#define W1S_OFF   8192
#define WHS_OFF   16384
#define P0_OFF    24576    // [16q][32 r] stride-18 x 16 lb = 9216 floats
#define P1_OFF    33792
#define RG_OFF    43008    // [2][32 r][16 lb] = 1024
#define WIH0_OFF  44032    // [32][4]
#define B0S_OFF   44160    // [32]
#define B1S_OFF   44192    // [32]
#define YW_OFF    44224    // [4][16]
#define WOUT_OFF  44288    // [2][256]
#define BO2_OFF   44800    // [2]
#define SMEM_BYTES ((44802) * 4)

__global__ void __launch_bounds__(NTHR, 1) lstm_all(
    const float* __restrict__ y,
    const float* __restrict__ Wih0, const float* __restrict__ Whh0,
    const float* __restrict__ bih0, const float* __restrict__ bhh0,
    const float* __restrict__ Wih1, const float* __restrict__ Whh1,
    const float* __restrict__ bih1, const float* __restrict__ bhh1,
    const float* __restrict__ Wout, const float* __restrict__ bout,
    float* __restrict__ out)
{
    extern __shared__ float sm[];
    float4* W0s4 = (float4*)(sm + W0S_OFF);
    float4* W1s4 = (float4*)(sm + W1S_OFF);
    float4* WHs4 = (float4*)(sm + WHS_OFF);
    float*  P0   = sm + P0_OFF;
    float*  P1   = sm + P1_OFF;
    float*  Rg   = sm + RG_OFF;
    float*  wih0 = sm + WIH0_OFF;
    float*  b0s  = sm + B0S_OFF;
    float*  b1s  = sm + B1S_OFF;
    float*  yw   = sm + YW_OFF;
    float*  wout = sm + WOUT_OFF;
    float*  bo2  = sm + BO2_OFF;

    const int tid  = threadIdx.x;
    const int bid  = blockIdx.x;
    const int grp  = bid >> 5;            // batch group 0..3
    const int gidx = bid & 31;            // CTA index within group
    const int B0   = grp * 16;            // first global batch of group
    const int j0   = gidx * 8;            // CTA owns hidden units j0..j0+7
    unsigned ls = 0;

    // ======== init: group-local global state ========
    {
        int gi = gidx * NTHR + tid;       // 0..16383 within group
        if (gi < 4096) {                  // zero h0 slot0 + h1 slot0 (group b-slice)
            int mp = gi >> 5, lb = (gi >> 1) & 15, e = gi & 1;
            g_h0[0][mp][B0 + lb][e] = 0.0f;
            g_h1[0][mp][B0 + lb][e] = 0.0f;
        }
        for (int i = gi; i < 4099 * 16; i += GCTAS * NTHR) {
            int row = i >> 4, lb = i & 15;
            g_yT[grp][row][lb] = (row < 3) ? -100.0f
                                           : y[(B0 + lb) * T_STEPS + (row - 3)];
        }
    }

    // ======== init: smem weights ([q][mp2][lr][rh] float4, rh = gate) ========
    for (int u = tid; u < 2048; u += NTHR) {
        int rh  = u & 3;
        int lr  = (u >> 2) & 7;
        int mp2 = (u >> 5) & 3;
        int q   = u >> 7;
        int row = rh * 256 + j0 + lr;
        int mb  = q * 16 + mp2 * 4;
        W0s4[u] = *(const float4*)(Whh0 + row * 256 + mb);
        W1s4[u] = *(const float4*)(Wih1 + row * 256 + mb);
        WHs4[u] = *(const float4*)(Whh1 + row * 256 + mb);
    }
    if (tid < 32) {                        // r = gate*8 + unit
        int row = (tid >> 3) * 256 + j0 + (tid & 7);
        b0s[tid] = bih0[row] + bhh0[row];
        b1s[tid] = bih1[row] + bhh1[row];
        for (int k = 0; k < 4; k++) wih0[tid * 4 + k] = Wih0[row * 4 + k];
    }
    wout[tid] = Wout[tid];                 // 512 elements
    if (tid < 2) bo2[tid] = bout[tid];

    // publish init-done (flag slot starts at 0 from previous run / load)
    __syncthreads();
    if (tid == 0) { __threadfence(); st_release(&g_flags[grp][gidx], 1u); }

    // ======== persistent 2-layer LSTM (per-group clock) ========
    const int q    = tid >> 5;             // m-chunk (16 m); warp-uniform
    const int lane = tid & 31;
    const int rh   = lane >> 3;            // gate 0..3
    const int bp   = lane & 7;             // local batch pair (batches 2bp,2bp+1)
    const int hfl  = q * 1024 + (grp * 8 + bp) * 4;   // float offset of K-pair

    // cell role (tid<256): layer, unit, local batch; c in a register
    const int clay = tid >> 7;             // 0/1 (for tid<256)
    const int cu   = (tid >> 4) & 7;
    const int clb  = tid & 15;
    float creg = 0.0f;

    for (int p = 0; p <= T_STEPS; p++) {
        // ---- group barrier wait: all 32 flags >= p+1 (one coalesced poll) ----
        if (tid < 32) {
            unsigned v = ld_acquire(&g_flags[grp][tid]);
            while (__ballot_sync(0xffffffffu, v < (unsigned)(p + 1)))
                v = ld_acquire(&g_flags[grp][tid]);
        }
        __syncthreads();

        const int s0 = p % 3;                       // h0(p-1)
        const int s1 = (p >= 1) ? (p - 1) : 0;      // h1(p-2); zeros at p=0
        const float* H0 = &g_h0[s0][0][0][0] + hfl;
        const float* H1 = &g_h1[s1][0][0][0] + hfl;
        if (tid < 64 && p < T_STEPS) yw[tid] = g_yT[grp][p + (tid >> 4)][tid & 15];

        ulonglong2 h0r[8], h1r[8];
        #pragma unroll
        for (int i = 0; i < 8; i++) h0r[i] = ldcg2(H0 + i * 128);
        #pragma unroll
        for (int i = 0; i < 8; i++) h1r[i] = ldcg2(H1 + i * 128);

        // ---- layer0: gate rh, 8 units, 16 m, 2 batches ----
        {
            ull aA[8], aB[8];
            #pragma unroll
            for (int lr = 0; lr < 8; lr++) { aA[lr] = 0ull; aB[lr] = 0ull; }
            #pragma unroll
            for (int mp2 = 0; mp2 < 4; mp2++) {
                const ulonglong2 hE = h0r[2 * mp2], hO = h0r[2 * mp2 + 1];
                #pragma unroll
                for (int lr = 0; lr < 8; lr++) {
                    ulonglong2 wp = *(const ulonglong2*)&W0s4[((q * 4 + mp2) * 8 + lr) * 4 + rh];
                    aA[lr] = ffma2(hE.x, wp.x, aA[lr]);
                    aB[lr] = ffma2(hE.y, wp.x, aB[lr]);
                    aA[lr] = ffma2(hO.x, wp.y, aA[lr]);
                    aB[lr] = ffma2(hO.y, wp.y, aB[lr]);
                }
            }
            #pragma unroll
            for (int lr = 0; lr < 8; lr++) {
                float2 v = make_float2(collapse2(aA[lr]), collapse2(aB[lr]));
                *(float2*)(P0 + (q * 32 + rh * 8 + lr) * 18 + 2 * bp) = v;
            }
        }
        // ---- layer1: W_ih1 x h0(p-1) + W_hh1 x h1(p-2) ----
        {
            ull aA[8], aB[8];
            #pragma unroll
            for (int lr = 0; lr < 8; lr++) { aA[lr] = 0ull; aB[lr] = 0ull; }
            #pragma unroll
            for (int mp2 = 0; mp2 < 4; mp2++) {
                const ulonglong2 hE = h0r[2 * mp2], hO = h0r[2 * mp2 + 1];
                #pragma unroll
                for (int lr = 0; lr < 8; lr++) {
                    ulonglong2 wp = *(const ulonglong2*)&W1s4[((q * 4 + mp2) * 8 + lr) * 4 + rh];
                    aA[lr] = ffma2(hE.x, wp.x, aA[lr]);
                    aB[lr] = ffma2(hE.y, wp.x, aB[lr]);
                    aA[lr] = ffma2(hO.x, wp.y, aA[lr]);
                    aB[lr] = ffma2(hO.y, wp.y, aB[lr]);
                }
            }
            #pragma unroll
            for (int mp2 = 0; mp2 < 4; mp2++) {
                const ulonglong2 hE = h1r[2 * mp2], hO = h1r[2 * mp2 + 1];
                #pragma unroll
                for (int lr = 0; lr < 8; lr++) {
                    ulonglong2 wp = *(const ulonglong2*)&WHs4[((q * 4 + mp2) * 8 + lr) * 4 + rh];
                    aA[lr] = ffma2(hE.x, wp.x, aA[lr]);
                    aB[lr] = ffma2(hE.y, wp.x, aB[lr]);
                    aA[lr] = ffma2(hO.x, wp.y, aA[lr]);
                    aB[lr] = ffma2(hO.y, wp.y, aB[lr]);
                }
            }
            #pragma unroll
            for (int lr = 0; lr < 8; lr++) {
                float2 v = make_float2(collapse2(aA[lr]), collapse2(aB[lr]));
                *(float2*)(P1 + (q * 32 + rh * 8 + lr) * 18 + 2 * bp) = v;
            }
        }
        __syncthreads();

        // ---- reduce 16 q-partials -> Rg (every thread handles 2 cells) ----
        #pragma unroll
        for (int cc = 0; cc < 2; cc++) {
            int c  = tid + cc * 512;
            int ly = c >> 9;
            int r  = (c >> 4) & 31;
            int lb = c & 15;
            const float* P = ly ? P1 : P0;
            float s = ly ? b1s[r] : b0s[r];
            #pragma unroll
            for (int qq = 0; qq < 16; qq++)
                s += P[(qq * 32 + r) * 18 + lb];
            if (!ly) {
                #pragma unroll
                for (int k = 0; k < 4; k++)
                    s = fmaf(yw[k * 16 + lb], wih0[r * 4 + k], s);
            }
            Rg[ly * 512 + r * 16 + lb] = s;
        }
        __syncthreads();

        // ---- cell update + publish h (tid < 256) ----
        if (tid < 256) {
            const bool act = clay ? (p >= 1) : (p < T_STEPS);
            if (act) {
                float gi = Rg[clay * 512 + (0 * 8 + cu) * 16 + clb];
                float gf = Rg[clay * 512 + (1 * 8 + cu) * 16 + clb];
                float gg = Rg[clay * 512 + (2 * 8 + cu) * 16 + clb];
                float go = Rg[clay * 512 + (3 * 8 + cu) * 16 + clb];
                creg = sigf(gf) * creg + sigf(gi) * tanh_f(gg);
                float h = sigf(go) * tanh_f(creg);
                int j = j0 + cu, b = B0 + clb;
                if (clay == 0) g_h0[(p + 1) % 3][j >> 1][b][j & 1] = h;  // h0(p)
                else           g_h1[p][j >> 1][b][j & 1]          = h;  // h1(p-1)
            }
        }
        __syncthreads();
        if (tid == 0) { __threadfence(); st_release(&g_flags[grp][gidx], (unsigned)(p + 2)); }
    }

    // ======== teardown: global barriers (2 rounds -> sense returns to 0) ========
    grid_barrier(tid, ls);                      // all polls finished everywhere
    if (tid == 0) st_relaxed(&g_flags[grp][gidx], 0u);   // reset for next replay
    grid_barrier(tid, ls);

    // ======== output projection: group batches only ========
    {
        const int t   = gidx * 128 + (tid >> 2);
        const int lb0 = (tid & 3) * 4;
        const float* h = &g_h1[t + 1][0][0][0];
        float s00 = bo2[0], s01 = bo2[1], s10 = bo2[0], s11 = bo2[1];
        float s20 = bo2[0], s21 = bo2[1], s30 = bo2[0], s31 = bo2[1];
        #pragma unroll 8
        for (int mp = 0; mp < 128; mp++) {
            float w0 = wout[2 * mp], w1 = wout[2 * mp + 1];
            float w2 = wout[256 + 2 * mp], w3 = wout[257 + 2 * mp];
            const float* hb = h + mp * 128 + (B0 + lb0) * 2;
            float2 v0 = *(const float2*)(hb + 0);
            float2 v1 = *(const float2*)(hb + 2);
            float2 v2 = *(const float2*)(hb + 4);
            float2 v3 = *(const float2*)(hb + 6);
            s00 += v0.x * w0 + v0.y * w1;  s01 += v0.x * w2 + v0.y * w3;
            s10 += v1.x * w0 + v1.y * w1;  s11 += v1.x * w2 + v1.y * w3;
            s20 += v2.x * w0 + v2.y * w1;  s21 += v2.x * w2 + v2.y * w3;
            s30 += v3.x * w0 + v3.y * w1;  s31 += v3.x * w2 + v3.y * w3;
        }
        int bg = B0 + lb0;
        out[(bg + 0) * (T_STEPS * 2) + t * 2 + 0] = s00;
        out[(bg + 0) * (T_STEPS * 2) + t * 2 + 1] = s01;
        out[(bg + 1) * (T_STEPS * 2) + t * 2 + 0] = s10;
        out[(bg + 1) * (T_STEPS * 2) + t * 2 + 1] = s11;
        out[(bg + 2) * (T_STEPS * 2) + t * 2 + 0] = s20;
        out[(bg + 2) * (T_STEPS * 2) + t * 2 + 1] = s21;
        out[(bg + 3) * (T_STEPS * 2) + t * 2 + 0] = s30;
        out[(bg + 3) * (T_STEPS * 2) + t * 2 + 1] = s31;
    }
}

// ---------------- launcher: ONE kernel ----------------
extern "C" void kernel_launch(void* const* d_in, const int* in_sizes, int n_in,
                              void* d_out, int out_size)
{
    (void)in_sizes; (void)n_in; (void)out_size;
    cudaFuncSetAttribute(lstm_all, cudaFuncAttributeMaxDynamicSharedMemorySize, SMEM_BYTES);
    lstm_all<<<NCTA, NTHR, SMEM_BYTES>>>(
        (const float*)d_in[0],
        (const float*)d_in[1], (const float*)d_in[2],
        (const float*)d_in[3], (const float*)d_in[4],
        (const float*)d_in[5], (const float*)d_in[6],
        (const float*)d_in[7], (const float*)d_in[8],
        (const float*)d_in[9], (const float*)d_in[10],
        (float*)d_out);
}

// round 15
// speedup vs baseline: 1.9589x; 1.3018x over previous
#include <cuda_runtime.h>

#define T_STEPS 4096
#define NCTA    128
#define NTHR    512

typedef unsigned long long ull;

// ---------------- global scratch (static; no allocs) ----------------
// h layout: [slot][mpair 0..127][b 0..63][2] -> element (m,b) at [m>>1][b][m&1]
__device__ __align__(256) float g_h0[2][128][64][2];     // h0(s) at slot s&1
__device__ __align__(256) float g_h1[4098][128][64][2];  // h1(s) at slot s+2; slots 0,1 zero
__device__ __align__(256) float g_yT[4099][64];          // yT[t+3][b] = y[b][t]; rows 0..2 pad
__device__ __align__(256) unsigned g_afl[NCTA];  // arrival flags; 0 between runs
__device__ unsigned g_go;     // release word; 0 between runs
__device__ unsigned g_cnt;    // legacy barrier; 0 between runs
__device__ unsigned g_sense;  // legacy barrier; 2 teardown rounds -> returns to 0

// ---------------- helpers ----------------
__device__ __forceinline__ ull ffma2(ull h, ull w, ull a) {
    ull d;
    asm("fma.rn.f32x2 %0, %1, %2, %3;" : "=l"(d) : "l"(h), "l"(w), "l"(a));
    return d;
}
__device__ __forceinline__ float collapse2(ull a) {   // even-m sum + odd-m sum
    return __uint_as_float((unsigned)a) + __uint_as_float((unsigned)(a >> 32));
}
__device__ __forceinline__ float sigf(float x)   { return 1.0f / (1.0f + __expf(-x)); }
__device__ __forceinline__ float tanh_f(float x) { return 2.0f * sigf(2.0f * x) - 1.0f; }

__device__ __forceinline__ ulonglong2 ldcg2(const float* p) {
    ulonglong2 v;
    asm volatile("ld.global.cg.v2.u64 {%0,%1}, [%2];" : "=l"(v.x), "=l"(v.y) : "l"(p));
    return v;
}
__device__ __forceinline__ unsigned atom_add_acqrel(unsigned* p, unsigned v) {
    unsigned old;
    asm volatile("atom.acq_rel.gpu.global.add.u32 %0, [%1], %2;"
                 : "=r"(old) : "l"(p), "r"(v) : "memory");
    return old;
}
__device__ __forceinline__ unsigned ld_acquire(const unsigned* p) {
    unsigned v;
    asm volatile("ld.acquire.gpu.global.u32 %0, [%1];" : "=r"(v) : "l"(p) : "memory");
    return v;
}
__device__ __forceinline__ uint4 ld_relaxed_v4(const unsigned* p) {
    uint4 v;
    asm volatile("ld.relaxed.gpu.global.v4.u32 {%0,%1,%2,%3}, [%4];"
                 : "=r"(v.x), "=r"(v.y), "=r"(v.z), "=r"(v.w) : "l"(p) : "memory");
    return v;
}
__device__ __forceinline__ void st_release(unsigned* p, unsigned v) {
    asm volatile("st.release.gpu.global.u32 [%0], %1;" :: "l"(p), "r"(v) : "memory");
}
__device__ __forceinline__ void st_relaxed(unsigned* p, unsigned v) {
    asm volatile("st.relaxed.gpu.global.u32 [%0], %1;" :: "l"(p), "r"(v) : "memory");
}
__device__ __forceinline__ void fence_acqrel_gpu() {
    asm volatile("fence.acq_rel.gpu;" ::: "memory");
}

// funnel-free two-level flag barrier; rn is a monotone round number (>=1)
__device__ __forceinline__ void flag_barrier(int tid, int bid, unsigned rn) {
    __syncthreads();
    if (tid == 0) st_release(&g_afl[bid], rn);       // parallel arrivals (no atomics)
    if (bid == 0) {
        if (tid < 32) {                              // one warp aggregates all 128 flags
            const unsigned* fp = g_afl + tid * 4;
            for (;;) {
                uint4 v = ld_relaxed_v4(fp);
                bool ok = (v.x >= rn) & (v.y >= rn) & (v.z >= rn) & (v.w >= rn);
                if (__all_sync(0xffffffffu, ok)) break;
            }
            if (tid == 0) { fence_acqrel_gpu(); st_release(&g_go, rn); }
        }
    } else {
        if (tid == 0) {
            while (ld_acquire(&g_go) < rn) { }
        }
    }
    __syncthreads();
}

// legacy atomic barrier — used exactly twice at teardown (resets itself)
__device__ __forceinline__ void grid_barrier(int tid, unsigned& ls) {
    __syncthreads();
    ls ^= 1u;
    if (tid == 0) {
        unsigned old = atom_add_acqrel(&g_cnt, 1u);
        if (old == NCTA - 1u) {
            st_relaxed(&g_cnt, 0u);
            st_release(&g_sense, ls);
        } else {
            while (ld_acquire(&g_sense) != ls) { }
        }
    }
    __syncthreads();
}

// ---------------- smem layout (floats) ----------------
//   W0s [8][256]    @ 0      (2048)  W_hh0 rows, plain fp32 K-major
//   W1s [8][256]    @ 2048   (2048)  W_ih1
//   WHs [8][256]    @ 4096   (2048)  W_hh1
//   P0  [16][8][64] @ 6144   (8192)  layer0 gate partials (q, row, batch)
//   P1  [16][8][64] @ 14336  (8192)
//   misc @ 22528: wih0[8][4]=32, b0s[8], b1s[8], yw[4][64]=256, wout[512], bo2[2]
#define SMEM_FLOATS (22528 + 818)
#define SMEM_BYTES  (SMEM_FLOATS * 4)

__global__ void __launch_bounds__(NTHR, 1) lstm_all(
    const float* __restrict__ y,
    const float* __restrict__ Wih0, const float* __restrict__ Whh0,
    const float* __restrict__ bih0, const float* __restrict__ bhh0,
    const float* __restrict__ Wih1, const float* __restrict__ Whh1,
    const float* __restrict__ bih1, const float* __restrict__ bhh1,
    const float* __restrict__ Wout, const float* __restrict__ bout,
    float* __restrict__ out)
{
    extern __shared__ float sm[];
    float* W0s  = sm;              // [8][256]
    float* W1s  = sm + 2048;       // [8][256]
    float* WHs  = sm + 4096;       // [8][256]
    float* P0   = sm + 6144;       // [16][8][64]
    float* P1   = sm + 14336;      // [16][8][64]
    float* wih0 = sm + 22528;      // [8][4]
    float* b0s  = wih0 + 32;       // [8]
    float* b1s  = b0s + 8;         // [8]
    float* yw   = b1s + 8;         // [4][64]
    float* wout = yw + 256;        // [2][256]
    float* bo2  = wout + 512;      // [2]

    const int tid = threadIdx.x;
    const int bid = blockIdx.x;
    const int j0  = bid * 2;                 // CTA owns hidden units j0, j0+1
    unsigned ls = 0;

    // ======== init: global state ========
    {
        int gi = bid * NTHR + tid;           // 0..65535
        if (gi < 32768) {
            ((float*)g_h0)[gi] = 0.0f;       // both h0 slots
            ((float*)g_h1)[gi] = 0.0f;       // h1 slots 0,1
        }
        for (int i = gi; i < 4099 * 64; i += NCTA * NTHR) {
            int row = i >> 6, b = i & 63;
            g_yT[row][b] = (row < 3) ? -100.0f : y[b * T_STEPS + (row - 3)];
        }
    }

    // ======== init: smem weights (plain fp32 rows) ========
    // local row r = gate*2 + lj ; global row = gate*256 + j0 + lj
    for (int idx = tid; idx < 8 * 256; idx += NTHR) {
        int r = idx >> 8, m = idx & 255;
        int row = (r >> 1) * 256 + j0 + (r & 1);
        W0s[idx] = Whh0[row * 256 + m];
        W1s[idx] = Wih1[row * 256 + m];
        WHs[idx] = Whh1[row * 256 + m];
    }
    if (tid < 8) {
        int row = (tid >> 1) * 256 + j0 + (tid & 1);
        b0s[tid] = bih0[row] + bhh0[row];
        b1s[tid] = bih1[row] + bhh1[row];
        for (int k = 0; k < 4; k++) wih0[tid * 4 + k] = Wih0[row * 4 + k];
    }
    wout[tid] = Wout[tid];                   // exactly 512 elements
    if (tid < 2) bo2[tid] = bout[tid];
    flag_barrier(tid, bid, 1u);              // round 1

    // ======== persistent 2-layer LSTM ========
    const int q    = tid >> 5;               // warp id = m-chunk (16 m per chunk)
    const int lane = tid & 31;                // batch pair: batches 2*lane, 2*lane+1
    const float* W0r = W0s + q * 16;          // + r*256 + mp2*4
    const float* W1r = W1s + q * 16;
    const float* WHr = WHs + q * 16;
    const int hfl = q * 8 * 128 + 4 * lane;   // float offset of thread's first K-pair

    // cell-update role (first 256 threads; c lives in a register)
    const int clb   = tid & 63;
    const int clj   = (tid >> 6) & 1;
    const int chalf = (tid >> 7) & 1;         // 0: layer0 cell, 1: layer1 cell
    float creg = 0.0f;

    for (int p = 0; p <= T_STEPS; p++) {
        const float* H0 = &g_h0[(p + 1) & 1][0][0][0] + hfl;  // h0(p-1)
        const float* H1 = &g_h1[p][0][0][0] + hfl;            // h1(p-2)
        if (tid < 256 && p < T_STEPS) yw[tid] = g_yT[p + (tid >> 6)][tid & 63];

        // h registers: [i].x = batch0 K-pair, [i].y = batch1 K-pair (mp = q*8+i)
        ulonglong2 h0r[8], h1r[8];
        #pragma unroll
        for (int i = 0; i < 8; i++) h0r[i] = ldcg2(H0 + i * 128);
        #pragma unroll
        for (int i = 0; i < 8; i++) h1r[i] = ldcg2(H1 + i * 128);

        // ---- layer0: 8 rows x 16 m x 2 batches ----
        {
            ull aA[8], aB[8];
            #pragma unroll
            for (int r = 0; r < 8; r++) { aA[r] = 0ull; aB[r] = 0ull; }
            #pragma unroll
            for (int mp2 = 0; mp2 < 4; mp2++) {
                const ulonglong2 hE = h0r[2 * mp2], hO = h0r[2 * mp2 + 1];
                #pragma unroll
                for (int r = 0; r < 8; r++) {
                    ulonglong2 wv = *(const ulonglong2*)(W0r + r * 256 + mp2 * 4);
                    aA[r] = ffma2(hE.x, wv.x, aA[r]);
                    aB[r] = ffma2(hE.y, wv.x, aB[r]);
                    aA[r] = ffma2(hO.x, wv.y, aA[r]);
                    aB[r] = ffma2(hO.y, wv.y, aB[r]);
                }
            }
            #pragma unroll
            for (int r = 0; r < 8; r++) {
                float2 v = make_float2(collapse2(aA[r]), collapse2(aB[r]));
                *(float2*)(P0 + q * 512 + r * 64 + 2 * lane) = v;
            }
        }
        // ---- layer1: W_ih1 x h0(p-1) + W_hh1 x h1(p-2) ----
        {
            ull aA[8], aB[8];
            #pragma unroll
            for (int r = 0; r < 8; r++) { aA[r] = 0ull; aB[r] = 0ull; }
            #pragma unroll
            for (int mp2 = 0; mp2 < 4; mp2++) {
                const ulonglong2 hE = h0r[2 * mp2], hO = h0r[2 * mp2 + 1];
                #pragma unroll
                for (int r = 0; r < 8; r++) {
                    ulonglong2 wv = *(const ulonglong2*)(W1r + r * 256 + mp2 * 4);
                    aA[r] = ffma2(hE.x, wv.x, aA[r]);
                    aB[r] = ffma2(hE.y, wv.x, aB[r]);
                    aA[r] = ffma2(hO.x, wv.y, aA[r]);
                    aB[r] = ffma2(hO.y, wv.y, aB[r]);
                }
            }
            #pragma unroll
            for (int mp2 = 0; mp2 < 4; mp2++) {
                const ulonglong2 hE = h1r[2 * mp2], hO = h1r[2 * mp2 + 1];
                #pragma unroll
                for (int r = 0; r < 8; r++) {
                    ulonglong2 wv = *(const ulonglong2*)(WHr + r * 256 + mp2 * 4);
                    aA[r] = ffma2(hE.x, wv.x, aA[r]);
                    aB[r] = ffma2(hE.y, wv.x, aB[r]);
                    aA[r] = ffma2(hO.x, wv.y, aA[r]);
                    aB[r] = ffma2(hO.y, wv.y, aB[r]);
                }
            }
            #pragma unroll
            for (int r = 0; r < 8; r++) {
                float2 v = make_float2(collapse2(aA[r]), collapse2(aB[r]));
                *(float2*)(P1 + q * 512 + r * 64 + 2 * lane) = v;
            }
        }
        __syncthreads();

        // ---- reduce 16 q-partials, cell update, publish h (first 256 threads) ----
        if (tid < 256) {
            const bool act = chalf ? (p > 0) : (p < T_STEPS);
            if (act) {
                const float* P  = chalf ? P1 : P0;
                const float* bs = chalf ? b1s : b0s;
                float gg[4];
                #pragma unroll
                for (int gt = 0; gt < 4; gt++) {
                    int r = gt * 2 + clj;
                    float s = bs[r];
                    #pragma unroll
                    for (int qq = 0; qq < 16; qq++)
                        s += P[qq * 512 + r * 64 + clb];
                    gg[gt] = s;
                }
                if (chalf == 0) {
                    #pragma unroll
                    for (int gt = 0; gt < 4; gt++) {
                        int r = gt * 2 + clj;
                        #pragma unroll
                        for (int k = 0; k < 4; k++)
                            gg[gt] = fmaf(yw[k * 64 + clb], wih0[r * 4 + k], gg[gt]);
                    }
                }
                creg = sigf(gg[1]) * creg + sigf(gg[0]) * tanh_f(gg[2]);
                float h = sigf(gg[3]) * tanh_f(creg);
                int j = j0 + clj;
                if (chalf == 0) g_h0[p & 1][j >> 1][clb][j & 1] = h;   // h0(p)
                else            g_h1[p + 1][j >> 1][clb][j & 1] = h;   // h1(p-1)
            }
        }
        flag_barrier(tid, bid, (unsigned)(p + 2));   // rounds 2..4098 (monotone)
    }

    // ======== teardown: reset flag state, legacy barriers return to 0 ========
    grid_barrier(tid, ls);                       // everyone past final flag use
    if (tid == 0) {
        st_relaxed(&g_afl[bid], 0u);             // reset own flag for next replay
        if (bid == 0) st_relaxed(&g_go, 0u);
    }
    grid_barrier(tid, ls);                       // 2 rounds -> g_sense back to 0

    // ======== output projection: out[b][t][k] = h1(t).Wout[k] + bout[k] ========
    {
        const int b  = tid & 63;
        const int tt = tid >> 6;    // 0..7
        #pragma unroll
        for (int u = 0; u < 4; u++) {
            int t = bid * 32 + tt * 4 + u;
            const float* h = &g_h1[t + 2][0][0][0] + b * 2;
            float s0 = bo2[0], s1 = bo2[1];
            #pragma unroll 8
            for (int mp = 0; mp < 128; mp++) {
                float2 v = *(const float2*)(h + mp * 128);
                s0 = fmaf(v.x, wout[2 * mp],       s0);
                s0 = fmaf(v.y, wout[2 * mp + 1],   s0);
                s1 = fmaf(v.x, wout[256 + 2 * mp], s1);
                s1 = fmaf(v.y, wout[257 + 2 * mp], s1);
            }
            out[b * (T_STEPS * 2) + t * 2 + 0] = s0;
            out[b * (T_STEPS * 2) + t * 2 + 1] = s1;
        }
    }
}

// ---------------- launcher: ONE kernel ----------------
extern "C" void kernel_launch(void* const* d_in, const int* in_sizes, int n_in,
                              void* d_out, int out_size)
{
    (void)in_sizes; (void)n_in; (void)out_size;
    cudaFuncSetAttribute(lstm_all, cudaFuncAttributeMaxDynamicSharedMemorySize, SMEM_BYTES);
    lstm_all<<<NCTA, NTHR, SMEM_BYTES>>>(
        (const float*)d_in[0],
        (const float*)d_in[1], (const float*)d_in[2],
        (const float*)d_in[3], (const float*)d_in[4],
        (const float*)d_in[5], (const float*)d_in[6],
        (const float*)d_in[7], (const float*)d_in[8],
        (const float*)d_in[9], (const float*)d_in[10],
        (float*)d_out);
}